// round 16
// baseline (speedup 1.0000x reference)
#include <cuda_runtime.h>
#include <cuda_bf16.h>
#include <cuda_fp16.h>
#include <math.h>
#include <float.h>
#include <stdint.h>

#define B_   2
#define T_   2048
#define C_   2048
#define H_   16
#define KVH_ 4
#define HD_  128
#define M_   (B_*T_)           // 4096
#define KG_  2048
#define NSM  148

// ---------------- scratch ----------------
__device__ __half g_xs [(size_t)M_ * KG_];
__device__ __half g_wb1[(size_t)3072 * KG_];
__device__ __half g_wb2[(size_t)2048 * KG_];
__device__ __half g_ys [(size_t)M_ * KG_];
__device__ __half g_q16[(size_t)M_ * 2048];
__device__ __half g_k2[(size_t)B_ * KVH_ * T_ * 128];
__device__ __half g_vt[(size_t)B_ * KVH_ * HD_ * T_];

// ---------------- helpers ----------------
__device__ __forceinline__ uint32_t smem_u32(const void* p) {
    uint32_t a;
    asm("{ .reg .u64 t; cvta.to.shared.u64 t, %1; cvt.u32.u64 %0, t; }" : "=r"(a) : "l"(p));
    return a;
}
#define LDMX4(r0, r1, r2, r3, addr) \
    asm volatile("ldmatrix.sync.aligned.m8n8.x4.shared.b16 {%0,%1,%2,%3}, [%4];" \
        : "=r"(r0), "=r"(r1), "=r"(r2), "=r"(r3) : "r"(addr))
#define MMA16816F16(c, a0, a1, a2, a3, b0, b1) \
    asm volatile("mma.sync.aligned.m16n8k16.row.col.f32.f16.f16.f32 " \
        "{%0,%1,%2,%3}, {%4,%5,%6,%7}, {%8,%9}, {%0,%1,%2,%3};" \
        : "+f"((c)[0]), "+f"((c)[1]), "+f"((c)[2]), "+f"((c)[3]) \
        : "r"(a0), "r"(a1), "r"(a2), "r"(a3), "r"(b0), "r"(b1))
#define CP_ASYNC16(dst, src) \
    asm volatile("cp.async.cg.shared.global [%0], [%1], 16;" :: "r"(dst), "l"(src) : "memory")
#define CP_COMMIT() asm volatile("cp.async.commit_group;" ::: "memory")
#define CP_WAIT(n)  asm volatile("cp.async.wait_group %0;" :: "n"(n) : "memory")

// ---------------- convert kernels ----------------
__global__ __launch_bounds__(256)
void conv_a_kernel(const float* __restrict__ src, __half* __restrict__ dst) {
    int idx = blockIdx.x * 256 + threadIdx.x;
    int m = idx >> 9;
    int k = (idx & 511) << 2;
    float4 v = *(const float4*)(src + (size_t)m * 2048 + k);
    __half2* d = (__half2*)(dst + (size_t)m * KG_ + k);
    d[0] = __floats2half2_rn(v.x, v.y);
    d[1] = __floats2half2_rn(v.z, v.w);
}

__global__ __launch_bounds__(256)
void tsplit_b_kernel(const float* __restrict__ src, __half* __restrict__ dst, int Ncols) {
    __shared__ float t[32][33];
    const int n0 = blockIdx.x * 32, k0 = blockIdx.y * 32;
    const int tx = threadIdx.x, ty = threadIdx.y;
#pragma unroll
    for (int i = 0; i < 4; i++)
        t[ty + i * 8][tx] = src[(size_t)(k0 + ty + i * 8) * Ncols + n0 + tx];
    __syncthreads();
#pragma unroll
    for (int i = 0; i < 4; i++)
        dst[(size_t)(n0 + ty + i * 8) * KG_ + k0 + tx] =
            __float2half_rn(t[tx][ty + i * 8]);
}

// ---------------- shared GEMM config ----------------
#define SMPAD 80
#define GASTG (256 * SMPAD)
#define GBSTG (128 * SMPAD)
#define GSTAGE_B (GASTG + GBSTG)        // 30720
#define GSMEM (4 * GSTAGE_B)            // 122880
#define EPAD 132

// ================= persistent QKV GEMM + fused rope/rms/V-transpose =================
__global__ __launch_bounds__(512, 1)
void gemm_qkv(const __half* __restrict__ A, const __half* __restrict__ Bt,
              const float* __restrict__ cosp, const float* __restrict__ sinp,
              __half* __restrict__ q16, __half* __restrict__ k2,
              __half* __restrict__ vt) {
    extern __shared__ uint8_t sm[];
    const uint32_t smb = smem_u32(sm);

    const int tid = threadIdx.x;
    const int lane = tid & 31, wid = tid >> 5;
    const int wm = wid >> 1, wn = wid & 1;
    const int crow = tid >> 2, c16 = tid & 3;
    const bool do_b = (crow < 128);

    const uint32_t sa0_rel = (uint32_t)(crow * SMPAD + c16 * 16);
    const uint32_t sa1_rel = sa0_rel + 128 * SMPAD;
    const uint32_t sb_rel  = (uint32_t)(GASTG + crow * SMPAD + c16 * 16);
    const int lj = lane >> 3, lr = lane & 7;
    const uint32_t a_rel = (uint32_t)((wm * 32 + ((lj & 1) << 3) + lr) * SMPAD + ((lj >> 1) << 4));
    const uint32_t b_rel = (uint32_t)(GASTG + (wn * 64 + ((lj >> 1) << 3) + lr) * SMPAD + ((lj & 1) << 4));
    const int cr = lane >> 2, cc = (lane & 3) << 1;
    const int nK = KG_ / 32;
    const int NT = 24 * 16;   // 384 tiles

    for (int tl = blockIdx.x; tl < NT; tl += gridDim.x) {
        const int nt = tl % 24;               // head/tile column
        const int tm = tl / 24;
        const int m0 = tm * 256, n0 = nt * 128;

        const __half* agp0 = A + (size_t)(m0 + crow) * KG_ + c16 * 8;
        const __half* agp1 = agp0 + (size_t)128 * KG_;
        const __half* bgp  = Bt + (size_t)(n0 + crow) * KG_ + c16 * 8;

        float acc[2][8][4];
#pragma unroll
        for (int i = 0; i < 2; i++)
#pragma unroll
            for (int j = 0; j < 8; j++)
#pragma unroll
                for (int r = 0; r < 4; r++) acc[i][j][r] = 0.0f;

        __syncthreads();   // prev tile's epilogue smem reads done
#pragma unroll
        for (int s = 0; s < 3; s++) {
            const uint32_t base = smb + s * GSTAGE_B;
            const int k0 = s * 32;
            CP_ASYNC16(base + sa0_rel, agp0 + k0);
            CP_ASYNC16(base + sa1_rel, agp1 + k0);
            if (do_b) CP_ASYNC16(base + sb_rel, bgp + k0);
            CP_COMMIT();
        }

        for (int it = 0; it < nK; it++) {
            CP_WAIT(2);
            __syncthreads();
            const int is = it + 3;
            if (is < nK) {
                const uint32_t base = smb + (is & 3) * GSTAGE_B;
                const int k0 = is * 32;
                CP_ASYNC16(base + sa0_rel, agp0 + k0);
                CP_ASYNC16(base + sa1_rel, agp1 + k0);
                if (do_b) CP_ASYNC16(base + sb_rel, bgp + k0);
            }
            CP_COMMIT();

            const uint32_t stg = smb + (it & 3) * GSTAGE_B;
#pragma unroll
            for (int kk = 0; kk < 2; kk++) {
                uint32_t af[2][4];
#pragma unroll
                for (int i = 0; i < 2; i++)
                    LDMX4(af[i][0], af[i][1], af[i][2], af[i][3],
                          stg + a_rel + i * 16 * SMPAD + kk * 32);
                uint32_t bf[8][2];
#pragma unroll
                for (int p = 0; p < 4; p++) {
                    uint32_t r0, r1, r2, r3;
                    LDMX4(r0, r1, r2, r3, stg + b_rel + p * 16 * SMPAD + kk * 32);
                    bf[2 * p][0] = r0; bf[2 * p][1] = r1;
                    bf[2 * p + 1][0] = r2; bf[2 * p + 1][1] = r3;
                }
#pragma unroll
                for (int i = 0; i < 2; i++)
#pragma unroll
                    for (int j = 0; j < 8; j++)
                        MMA16816F16(acc[i][j], af[i][0], af[i][1], af[i][2], af[i][3],
                                    bf[j][0], bf[j][1]);
            }
        }
        CP_WAIT(0);

        // ---- fused epilogue: two 128-row halves ----
        float* tile = (float*)sm;
#pragma unroll 1
        for (int half = 0; half < 2; half++) {
            __syncthreads();
            if ((wm >> 2) == half) {
                const int lwm = wm & 3;
#pragma unroll
                for (int i = 0; i < 2; i++) {
                    const int row = lwm * 32 + i * 16 + cr;
#pragma unroll
                    for (int j = 0; j < 8; j++) {
                        const int col = wn * 64 + j * 8 + cc;
                        tile[row * EPAD + col]           = acc[i][j][0];
                        tile[row * EPAD + col + 1]       = acc[i][j][1];
                        tile[(row + 8) * EPAD + col]     = acc[i][j][2];
                        tile[(row + 8) * EPAD + col + 1] = acc[i][j][3];
                    }
                }
            }
            __syncthreads();

            const int mbase = m0 + half * 128;
            if (nt < 20) {
                const int r = tid >> 2, q = tid & 3;
                const int mrow = mbase + r;
                const int t = mrow & (T_ - 1);
                float o1v[16], o2v[16];
                float ss = 0.0f;
#pragma unroll
                for (int i = 0; i < 16; i += 4) {
                    float4 x1 = *(float4*)&tile[r * EPAD + q * 16 + i];
                    float4 x2 = *(float4*)&tile[r * EPAD + 64 + q * 16 + i];
                    float4 cv = *(const float4*)(cosp + t * 64 + q * 16 + i);
                    float4 sv = *(const float4*)(sinp + t * 64 + q * 16 + i);
                    o1v[i]     = x1.x * cv.x + x2.x * sv.x;
                    o2v[i]     = x2.x * cv.x - x1.x * sv.x;
                    o1v[i + 1] = x1.y * cv.y + x2.y * sv.y;
                    o2v[i + 1] = x2.y * cv.y - x1.y * sv.y;
                    o1v[i + 2] = x1.z * cv.z + x2.z * sv.z;
                    o2v[i + 2] = x2.z * cv.z - x1.z * sv.z;
                    o1v[i + 3] = x1.w * cv.w + x2.w * sv.w;
                    o2v[i + 3] = x2.w * cv.w - x1.w * sv.w;
#pragma unroll
                    for (int e = 0; e < 4; e++)
                        ss += o1v[i + e] * o1v[i + e] + o2v[i + e] * o2v[i + e];
                }
                ss += __shfl_xor_sync(0xffffffffu, ss, 1);
                ss += __shfl_xor_sync(0xffffffffu, ss, 2);
                const float rn = rsqrtf(ss * (1.0f / 128.0f) + 1e-5f);

                __half* dst = (nt < 16)
                    ? (q16 + (size_t)mrow * 2048 + (size_t)nt * 128)
                    : (k2 + ((size_t)((mrow >> 11) * KVH_ + (nt - 16)) * T_ + t) * 128);
                __half2 w1[8], w2[8];
#pragma unroll
                for (int i = 0; i < 8; i++) {
                    w1[i] = __floats2half2_rn(o1v[2 * i] * rn, o1v[2 * i + 1] * rn);
                    w2[i] = __floats2half2_rn(o2v[2 * i] * rn, o2v[2 * i + 1] * rn);
                }
                *(uint4*)(dst + q * 16)          = *(uint4*)&w1[0];
                *(uint4*)(dst + q * 16 + 8)      = *(uint4*)&w1[4];
                *(uint4*)(dst + 64 + q * 16)     = *(uint4*)&w2[0];
                *(uint4*)(dst + 64 + q * 16 + 8) = *(uint4*)&w2[4];
            } else {
                const int d = tid >> 2, rc = tid & 3;
                const int kvh = nt - 20;
                const int b = mbase >> 11;
                const int t0 = mbase & (T_ - 1);
                __half hv[32];
#pragma unroll
                for (int rr = 0; rr < 32; rr++)
                    hv[rr] = __float2half_rn(tile[(rc * 32 + rr) * EPAD + d]);
                __half* dst = vt + ((size_t)(b * KVH_ + kvh) * 128 + d) * T_ + t0 + rc * 32;
#pragma unroll
                for (int c = 0; c < 4; c++)
                    *(uint4*)(dst + c * 8) = *(uint4*)&hv[c * 8];
            }
        }
    }
}

// ================= persistent plain fp16 GEMM (output projection) =================
__global__ __launch_bounds__(512, 1)
void gemm_f16(const __half* __restrict__ A, const __half* __restrict__ Bt,
              float* __restrict__ C, int N) {
    extern __shared__ uint8_t sm[];
    const uint32_t smb = smem_u32(sm);

    const int tid = threadIdx.x;
    const int lane = tid & 31, wid = tid >> 5;
    const int wm = wid >> 1, wn = wid & 1;
    const int crow = tid >> 2, c16 = tid & 3;
    const bool do_b = (crow < 128);

    const uint32_t sa0_rel = (uint32_t)(crow * SMPAD + c16 * 16);
    const uint32_t sa1_rel = sa0_rel + 128 * SMPAD;
    const uint32_t sb_rel  = (uint32_t)(GASTG + crow * SMPAD + c16 * 16);
    const int lj = lane >> 3, lr = lane & 7;
    const uint32_t a_rel = (uint32_t)((wm * 32 + ((lj & 1) << 3) + lr) * SMPAD + ((lj >> 1) << 4));
    const uint32_t b_rel = (uint32_t)(GASTG + (wn * 64 + ((lj >> 1) << 3) + lr) * SMPAD + ((lj & 1) << 4));
    const int cr = lane >> 2, cc = (lane & 3) << 1;
    const int nK = KG_ / 32;
    const int nTileN = N / 128;
    const int NT = nTileN * (M_ / 256);

    for (int tl = blockIdx.x; tl < NT; tl += gridDim.x) {
        const int tn = tl % nTileN, tm = tl / nTileN;
        const int m0 = tm * 256, n0 = tn * 128;

        const __half* agp0 = A + (size_t)(m0 + crow) * KG_ + c16 * 8;
        const __half* agp1 = agp0 + (size_t)128 * KG_;
        const __half* bgp  = Bt + (size_t)(n0 + crow) * KG_ + c16 * 8;

        float acc[2][8][4];
#pragma unroll
        for (int i = 0; i < 2; i++)
#pragma unroll
            for (int j = 0; j < 8; j++)
#pragma unroll
                for (int r = 0; r < 4; r++) acc[i][j][r] = 0.0f;

        __syncthreads();
#pragma unroll
        for (int s = 0; s < 3; s++) {
            const uint32_t base = smb + s * GSTAGE_B;
            const int k0 = s * 32;
            CP_ASYNC16(base + sa0_rel, agp0 + k0);
            CP_ASYNC16(base + sa1_rel, agp1 + k0);
            if (do_b) CP_ASYNC16(base + sb_rel, bgp + k0);
            CP_COMMIT();
        }

        for (int it = 0; it < nK; it++) {
            CP_WAIT(2);
            __syncthreads();
            const int is = it + 3;
            if (is < nK) {
                const uint32_t base = smb + (is & 3) * GSTAGE_B;
                const int k0 = is * 32;
                CP_ASYNC16(base + sa0_rel, agp0 + k0);
                CP_ASYNC16(base + sa1_rel, agp1 + k0);
                if (do_b) CP_ASYNC16(base + sb_rel, bgp + k0);
            }
            CP_COMMIT();

            const uint32_t stg = smb + (it & 3) * GSTAGE_B;
#pragma unroll
            for (int kk = 0; kk < 2; kk++) {
                uint32_t af[2][4];
#pragma unroll
                for (int i = 0; i < 2; i++)
                    LDMX4(af[i][0], af[i][1], af[i][2], af[i][3],
                          stg + a_rel + i * 16 * SMPAD + kk * 32);
                uint32_t bf[8][2];
#pragma unroll
                for (int p = 0; p < 4; p++) {
                    uint32_t r0, r1, r2, r3;
                    LDMX4(r0, r1, r2, r3, stg + b_rel + p * 16 * SMPAD + kk * 32);
                    bf[2 * p][0] = r0; bf[2 * p][1] = r1;
                    bf[2 * p + 1][0] = r2; bf[2 * p + 1][1] = r3;
                }
#pragma unroll
                for (int i = 0; i < 2; i++)
#pragma unroll
                    for (int j = 0; j < 8; j++)
                        MMA16816F16(acc[i][j], af[i][0], af[i][1], af[i][2], af[i][3],
                                    bf[j][0], bf[j][1]);
            }
        }
        CP_WAIT(0);

#pragma unroll
        for (int i = 0; i < 2; i++) {
            const int mrow = m0 + wm * 32 + i * 16 + cr;
#pragma unroll
            for (int j = 0; j < 8; j++) {
                const int col = n0 + wn * 64 + j * 8 + cc;
                *(float2*)(C + (size_t)mrow * N + col)       = make_float2(acc[i][j][0], acc[i][j][1]);
                *(float2*)(C + (size_t)(mrow + 8) * N + col) = make_float2(acc[i][j][2], acc[i][j][3]);
            }
        }
    }
}

// ---------------- tensor-core flash attention (pure fp16) ----------------
#define AKS 272
#define AVS2 144
#define SM_Q   0
#define SM_K0  (64 * AKS)
#define SM_K1  (SM_K0 + 64 * AKS)
#define SM_V0  (SM_K1 + 64 * AKS)
#define SM_V1  (SM_V0 + 128 * AVS2)
#define SM_RED (SM_V1 + 128 * AVS2)
#define ATT_SMEM (SM_RED + 1024)       // 90112
#define ATT_SCALE 0.08838834764831845f

__global__ __launch_bounds__(256, 2)
void attn_mma_kernel(const __half* __restrict__ q16,
                     const __half* __restrict__ k2,
                     const __half* __restrict__ vt,
                     __half* __restrict__ ys) {
    extern __shared__ uint8_t sm[];
    const uint32_t smb = smem_u32(sm);
    float* redmax = (float*)(sm + SM_RED);
    float* redsum = (float*)(sm + SM_RED + 512);

    const int tid = threadIdx.x;
    const int lane = tid & 31, wid = tid >> 5;
    const int wm = wid >> 1, wn = wid & 1;
    const int qtile = 31 - blockIdx.x;
    const int bh = blockIdx.y;
    const int b  = bh >> 4;
    const int h  = bh & 15;
    const int kv = h >> 2;
    const int q0 = qtile * 64;

    const __half* k2b = k2 + (size_t)(b * KVH_ + kv) * T_ * 128;
    const __half* vtb = vt + (size_t)(b * KVH_ + kv) * 128 * T_;
    const __half* q16b = q16 + (size_t)(b * T_ + q0) * 2048 + (size_t)h * 128;

    const int krow = tid >> 2, kc = tid & 3;
    const int vrow = tid >> 1, vc = tid & 1;
    const uint32_t kdst_rel = (uint32_t)(krow * AKS);
    const uint32_t vdst_rel = (uint32_t)(vrow * AVS2);

    {
#pragma unroll
        for (int i = 0; i < 4; i++) {
            int c = kc + i * 4;
            CP_ASYNC16(smb + SM_Q + kdst_rel + c * 16, q16b + (size_t)krow * 2048 + c * 8);
        }
        const __half* src = k2b + (size_t)krow * 128;
#pragma unroll
        for (int i = 0; i < 4; i++) {
            int c = kc + i * 4;
            CP_ASYNC16(smb + SM_K0 + kdst_rel + c * 16, src + c * 8);
        }
        const __half* srow = vtb + (size_t)vrow * T_;
#pragma unroll
        for (int i = 0; i < 4; i++) {
            int c = vc + i * 2;
            CP_ASYNC16(smb + SM_V0 + vdst_rel + c * 16, srow + c * 8);
        }
        CP_COMMIT();
    }

    const int lj = lane >> 3, lr = lane & 7;
    const uint32_t a_off = smb + SM_Q + (uint32_t)((wm * 16 + ((lj & 1) << 3) + lr) * AKS + ((lj >> 1) << 4));
    const uint32_t b_rel = (uint32_t)((wn * 32 + ((lj >> 1) << 3) + lr) * AKS + ((lj & 1) << 4));
    const uint32_t v_rel = (uint32_t)((((lj >> 1) << 3) + lr) * AVS2 + ((lj & 1) << 4));

    const int ra = lane >> 2;
    const int row_a = wm * 16 + ra, row_b = row_a + 8;
    const int colb = wn * 32 + 2 * (lane & 3);
    float m_a = -FLT_MAX, m_b = -FLT_MAX, l_a = 0.0f, l_b = 0.0f;

    float o[16][4];
#pragma unroll
    for (int j = 0; j < 16; j++)
#pragma unroll
        for (int r = 0; r < 4; r++) o[j][r] = 0.0f;

    for (int jt = 0; jt <= qtile; jt++) {
        const int buf = jt & 1;
        const uint32_t sK = smb + (buf ? SM_K1 : SM_K0);
        const uint32_t sV = smb + (buf ? SM_V1 : SM_V0);

        CP_WAIT(0);
        __syncthreads();

        if (jt < qtile) {
            const int j1 = (jt + 1) * 64;
            const uint32_t dK = smb + (buf ? SM_K0 : SM_K1);
            const uint32_t dV = smb + (buf ? SM_V0 : SM_V1);
            const __half* src = k2b + (size_t)(j1 + krow) * 128;
#pragma unroll
            for (int i = 0; i < 4; i++) {
                int c = kc + i * 4;
                CP_ASYNC16(dK + kdst_rel + c * 16, src + c * 8);
            }
            const __half* srow = vtb + (size_t)vrow * T_ + j1;
#pragma unroll
            for (int i = 0; i < 4; i++) {
                int c = vc + i * 2;
                CP_ASYNC16(dV + vdst_rel + c * 16, srow + c * 8);
            }
        }
        CP_COMMIT();

        float s_[4][4];
#pragma unroll
        for (int j = 0; j < 4; j++)
#pragma unroll
            for (int r = 0; r < 4; r++) s_[j][r] = 0.0f;

#pragma unroll
        for (int kk = 0; kk < 8; kk++) {
            uint32_t af[4];
            LDMX4(af[0], af[1], af[2], af[3], a_off + 32 * kk);
            uint32_t bf[4][2];
#pragma unroll
            for (int p = 0; p < 2; p++) {
                uint32_t r0, r1, r2, r3;
                LDMX4(r0, r1, r2, r3, sK + b_rel + p * 16 * AKS + 32 * kk);
                bf[2 * p][0] = r0; bf[2 * p][1] = r1;
                bf[2 * p + 1][0] = r2; bf[2 * p + 1][1] = r3;
            }
#pragma unroll
            for (int j = 0; j < 4; j++)
                MMA16816F16(s_[j], af[0], af[1], af[2], af[3], bf[j][0], bf[j][1]);
        }

        const bool diag = (jt == qtile);
        float mxa = -FLT_MAX, mxb = -FLT_MAX;
#pragma unroll
        for (int j = 0; j < 4; j++)
#pragma unroll
            for (int e = 0; e < 2; e++) {
                int cg = colb + 8 * j + e;
                float va = s_[j][e] * ATT_SCALE;
                if (diag && cg > row_a) va = -FLT_MAX;
                s_[j][e] = va; mxa = fmaxf(mxa, va);
                float vb = s_[j][e + 2] * ATT_SCALE;
                if (diag && cg > row_b) vb = -FLT_MAX;
                s_[j][e + 2] = vb; mxb = fmaxf(mxb, vb);
            }
        mxa = fmaxf(mxa, __shfl_xor_sync(0xffffffffu, mxa, 1));
        mxa = fmaxf(mxa, __shfl_xor_sync(0xffffffffu, mxa, 2));
        mxb = fmaxf(mxb, __shfl_xor_sync(0xffffffffu, mxb, 1));
        mxb = fmaxf(mxb, __shfl_xor_sync(0xffffffffu, mxb, 2));
        if ((lane & 3) == 0) {
            redmax[wn * 64 + row_a] = mxa;
            redmax[wn * 64 + row_b] = mxb;
        }
        __syncthreads();
        float mna = fmaxf(m_a, fmaxf(redmax[row_a], redmax[64 + row_a]));
        float mnb = fmaxf(m_b, fmaxf(redmax[row_b], redmax[64 + row_b]));
        float fa = __expf(m_a - mna), fb = __expf(m_b - mnb);
        float sa = 0.0f, sb = 0.0f;
#pragma unroll
        for (int j = 0; j < 4; j++)
#pragma unroll
            for (int e = 0; e < 2; e++) {
                float pa = __expf(s_[j][e] - mna);
                s_[j][e] = pa; sa += pa;
                float pb = __expf(s_[j][e + 2] - mnb);
                s_[j][e + 2] = pb; sb += pb;
            }
        sa += __shfl_xor_sync(0xffffffffu, sa, 1);
        sa += __shfl_xor_sync(0xffffffffu, sa, 2);
        sb += __shfl_xor_sync(0xffffffffu, sb, 1);
        sb += __shfl_xor_sync(0xffffffffu, sb, 2);
        if ((lane & 3) == 0) {
            redsum[wn * 64 + row_a] = sa;
            redsum[wn * 64 + row_b] = sb;
        }
        __syncthreads();
        l_a = l_a * fa + redsum[row_a] + redsum[64 + row_a];
        l_b = l_b * fb + redsum[row_b] + redsum[64 + row_b];
        m_a = mna; m_b = mnb;

#pragma unroll
        for (int j = 0; j < 16; j++) {
            o[j][0] *= fa; o[j][1] *= fa;
            o[j][2] *= fb; o[j][3] *= fb;
        }

        uint32_t php0[4], php1[4];
#pragma unroll
        for (int j = 0; j < 4; j++) {
            __half2 h01 = __floats2half2_rn(s_[j][0], s_[j][1]);
            __half2 h23 = __floats2half2_rn(s_[j][2], s_[j][3]);
            php0[j] = *(uint32_t*)&h01;
            php1[j] = *(uint32_t*)&h23;
        }

        {
            const uint32_t bbase = wn * 64u;
#pragma unroll
            for (int kk2 = 0; kk2 < 2; kk2++) {
                uint32_t a0 = php0[2 * kk2];
                uint32_t a1 = php1[2 * kk2];
                uint32_t a2 = php0[2 * kk2 + 1];
                uint32_t a3 = php1[2 * kk2 + 1];
                uint32_t vb[16][2];
#pragma unroll
                for (int p = 0; p < 8; p++) {
                    uint32_t r0, r1, r2, r3;
                    LDMX4(r0, r1, r2, r3, sV + v_rel + p * 16 * AVS2 + bbase + 32 * kk2);
                    vb[2 * p][0] = r0; vb[2 * p][1] = r1;
                    vb[2 * p + 1][0] = r2; vb[2 * p + 1][1] = r3;
                }
#pragma unroll
                for (int j = 0; j < 16; j++)
                    MMA16816F16(o[j], a0, a1, a2, a3, vb[j][0], vb[j][1]);
            }
        }
    }

    __syncthreads();
    float* Ob = (float*)sm;
    if (wn == 1) {
#pragma unroll
        for (int j = 0; j < 16; j++) {
            int col = 8 * j + 2 * (lane & 3);
            *(float2*)&Ob[row_a * 132 + col] = make_float2(o[j][0], o[j][1]);
            *(float2*)&Ob[row_b * 132 + col] = make_float2(o[j][2], o[j][3]);
        }
    }
    __syncthreads();
    if (wn == 0) {
        float inva = 1.0f / l_a, invb = 1.0f / l_b;
        __half* base = ys + (size_t)(b * T_ + q0) * KG_ + h * 128;
#pragma unroll
        for (int j = 0; j < 16; j++) {
            int col = 8 * j + 2 * (lane & 3);
            float2 pa = *(float2*)&Ob[row_a * 132 + col];
            float2 pb = *(float2*)&Ob[row_b * 132 + col];
            *(__half2*)(base + (size_t)row_a * KG_ + col) =
                __floats2half2_rn((o[j][0] + pa.x) * inva, (o[j][1] + pa.y) * inva);
            *(__half2*)(base + (size_t)row_b * KG_ + col) =
                __floats2half2_rn((o[j][2] + pb.x) * invb, (o[j][3] + pb.y) * invb);
        }
    }
}

// ---------------- launch ----------------
extern "C" void kernel_launch(void* const* d_in, const int* in_sizes, int n_in,
                              void* d_out, int out_size) {
    const float* x    = (const float*)d_in[0];
    const float* cosp = (const float*)d_in[1];
    const float* sinp = (const float*)d_in[2];
    const float* wq   = (const float*)d_in[3];
    const float* wk   = (const float*)d_in[4];
    const float* wv   = (const float*)d_in[5];
    const float* wo   = (const float*)d_in[6];
    float* out = (float*)d_out;

    __half *xs, *wb1, *wb2, *ys, *q16, *k2, *vt;
    cudaGetSymbolAddress((void**)&xs,  g_xs);
    cudaGetSymbolAddress((void**)&wb1, g_wb1);
    cudaGetSymbolAddress((void**)&wb2, g_wb2);
    cudaGetSymbolAddress((void**)&ys,  g_ys);
    cudaGetSymbolAddress((void**)&q16, g_q16);
    cudaGetSymbolAddress((void**)&k2,  g_k2);
    cudaGetSymbolAddress((void**)&vt,  g_vt);

    cudaFuncSetAttribute(attn_mma_kernel, cudaFuncAttributeMaxDynamicSharedMemorySize, ATT_SMEM);
    cudaFuncSetAttribute(gemm_f16, cudaFuncAttributeMaxDynamicSharedMemorySize, GSMEM);
    cudaFuncSetAttribute(gemm_qkv, cudaFuncAttributeMaxDynamicSharedMemorySize, GSMEM);

    dim3 tb(32, 8);
    conv_a_kernel<<<(M_ * 2048 / 4) / 256, 256>>>(x, xs);
    tsplit_b_kernel<<<dim3(2048 / 32, 2048 / 32), tb>>>(wq, wb1, 2048);
    tsplit_b_kernel<<<dim3(512  / 32, 2048 / 32), tb>>>(wk, wb1 + (size_t)2048 * KG_, 512);
    tsplit_b_kernel<<<dim3(512  / 32, 2048 / 32), tb>>>(wv, wb1 + (size_t)2560 * KG_, 512);
    tsplit_b_kernel<<<dim3(2048 / 32, 2048 / 32), tb>>>(wo, wb2, 2048);

    gemm_qkv<<<NSM, 512, GSMEM>>>(xs, wb1, cosp, sinp, q16, k2, vt);
    attn_mma_kernel<<<dim3(32, 32), 256, ATT_SMEM>>>(q16, k2, vt, ys);
    gemm_f16<<<NSM, 512, GSMEM>>>(ys, wb2, out, 2048);
}

// round 17
// speedup vs baseline: 1.0018x; 1.0018x over previous
#include <cuda_runtime.h>
#include <cuda_bf16.h>
#include <cuda_fp16.h>
#include <math.h>
#include <float.h>
#include <stdint.h>

#define B_   2
#define T_   2048
#define C_   2048
#define H_   16
#define KVH_ 4
#define HD_  128
#define M_   (B_*T_)           // 4096
#define KG_  2048
#define QKV_LD 3072

// ---------------- scratch ----------------
__device__ __half g_xs [(size_t)M_ * KG_];
__device__ __half g_wb1[(size_t)3072 * KG_];
__device__ __half g_wb2[(size_t)2048 * KG_];
__device__ __half g_ys [(size_t)M_ * KG_];
__device__ __half g_q16[(size_t)M_ * 2048];
__device__ __half g_k2[(size_t)B_ * KVH_ * T_ * 128];
__device__ __half g_vt[(size_t)B_ * KVH_ * HD_ * T_];

// ---------------- helpers ----------------
__device__ __forceinline__ uint32_t smem_u32(const void* p) {
    uint32_t a;
    asm("{ .reg .u64 t; cvta.to.shared.u64 t, %1; cvt.u32.u64 %0, t; }" : "=r"(a) : "l"(p));
    return a;
}
#define LDMX4(r0, r1, r2, r3, addr) \
    asm volatile("ldmatrix.sync.aligned.m8n8.x4.shared.b16 {%0,%1,%2,%3}, [%4];" \
        : "=r"(r0), "=r"(r1), "=r"(r2), "=r"(r3) : "r"(addr))
#define MMA16816F16(c, a0, a1, a2, a3, b0, b1) \
    asm volatile("mma.sync.aligned.m16n8k16.row.col.f32.f16.f16.f32 " \
        "{%0,%1,%2,%3}, {%4,%5,%6,%7}, {%8,%9}, {%0,%1,%2,%3};" \
        : "+f"((c)[0]), "+f"((c)[1]), "+f"((c)[2]), "+f"((c)[3]) \
        : "r"(a0), "r"(a1), "r"(a2), "r"(a3), "r"(b0), "r"(b1))
#define CP_ASYNC16(dst, src) \
    asm volatile("cp.async.cg.shared.global [%0], [%1], 16;" :: "r"(dst), "l"(src) : "memory")
#define CP_COMMIT() asm volatile("cp.async.commit_group;" ::: "memory")
#define CP_WAIT(n)  asm volatile("cp.async.wait_group %0;" :: "n"(n) : "memory")

// ---------------- convert kernels ----------------
__global__ __launch_bounds__(256)
void conv_a_kernel(const float* __restrict__ src, __half* __restrict__ dst) {
    int idx = blockIdx.x * 256 + threadIdx.x;
    int m = idx >> 9;
    int k = (idx & 511) << 2;
    float4 v = *(const float4*)(src + (size_t)m * 2048 + k);
    __half2* d = (__half2*)(dst + (size_t)m * KG_ + k);
    d[0] = __floats2half2_rn(v.x, v.y);
    d[1] = __floats2half2_rn(v.z, v.w);
}

__global__ __launch_bounds__(256)
void tsplit_b_kernel(const float* __restrict__ src, __half* __restrict__ dst, int Ncols) {
    __shared__ float t[32][33];
    const int n0 = blockIdx.x * 32, k0 = blockIdx.y * 32;
    const int tx = threadIdx.x, ty = threadIdx.y;
#pragma unroll
    for (int i = 0; i < 4; i++)
        t[ty + i * 8][tx] = src[(size_t)(k0 + ty + i * 8) * Ncols + n0 + tx];
    __syncthreads();
#pragma unroll
    for (int i = 0; i < 4; i++)
        dst[(size_t)(n0 + ty + i * 8) * KG_ + k0 + tx] =
            __float2half_rn(t[tx][ty + i * 8]);
}

// ---------------- shared GEMM config ----------------
#define SMPAD 80
#define GASTG (256 * SMPAD)
#define GBSTG (128 * SMPAD)
#define GSTAGE_B (GASTG + GBSTG)        // 30720
#define GSMEM (4 * GSTAGE_B)            // 122880
#define EPAD 132

// ================= QKV GEMM with fused rope/rms/V-transpose epilogue =================
__global__ __launch_bounds__(512, 1)
void gemm_qkv(const __half* __restrict__ A, const __half* __restrict__ Bt,
              const float* __restrict__ cosp, const float* __restrict__ sinp,
              __half* __restrict__ q16, __half* __restrict__ k2,
              __half* __restrict__ vt) {
    extern __shared__ uint8_t sm[];
    const uint32_t smb = smem_u32(sm);

    const int tid = threadIdx.x;
    const int lane = tid & 31, wid = tid >> 5;
    const int wm = wid >> 1, wn = wid & 1;
    const int m0 = blockIdx.y * 256, n0 = blockIdx.x * 128;

    const int crow = tid >> 2, c16 = tid & 3;
    const __half* agp0 = A + (size_t)(m0 + crow) * KG_ + c16 * 8;
    const __half* agp1 = agp0 + (size_t)128 * KG_;
    const __half* bgp  = Bt + (size_t)(n0 + crow) * KG_ + c16 * 8;
    const uint32_t sa0_rel = (uint32_t)(crow * SMPAD + c16 * 16);
    const uint32_t sa1_rel = sa0_rel + 128 * SMPAD;
    const uint32_t sb_rel  = (uint32_t)(GASTG + crow * SMPAD + c16 * 16);
    const bool do_b = (crow < 128);

    float acc[2][8][4];
#pragma unroll
    for (int i = 0; i < 2; i++)
#pragma unroll
        for (int j = 0; j < 8; j++)
#pragma unroll
            for (int r = 0; r < 4; r++) acc[i][j][r] = 0.0f;

    const int nK = KG_ / 32;

#pragma unroll
    for (int s = 0; s < 3; s++) {
        const uint32_t base = smb + s * GSTAGE_B;
        const int k0 = s * 32;
        CP_ASYNC16(base + sa0_rel, agp0 + k0);
        CP_ASYNC16(base + sa1_rel, agp1 + k0);
        if (do_b) CP_ASYNC16(base + sb_rel, bgp + k0);
        CP_COMMIT();
    }

    const int lj = lane >> 3, lr = lane & 7;
    const uint32_t a_rel = (uint32_t)((wm * 32 + ((lj & 1) << 3) + lr) * SMPAD + ((lj >> 1) << 4));
    const uint32_t b_rel = (uint32_t)(GASTG + (wn * 64 + ((lj >> 1) << 3) + lr) * SMPAD + ((lj & 1) << 4));

    for (int it = 0; it < nK; it++) {
        CP_WAIT(2);
        __syncthreads();
        const int is = it + 3;
        if (is < nK) {
            const uint32_t base = smb + (is & 3) * GSTAGE_B;
            const int k0 = is * 32;
            CP_ASYNC16(base + sa0_rel, agp0 + k0);
            CP_ASYNC16(base + sa1_rel, agp1 + k0);
            if (do_b) CP_ASYNC16(base + sb_rel, bgp + k0);
        }
        CP_COMMIT();

        const uint32_t stg = smb + (it & 3) * GSTAGE_B;
#pragma unroll
        for (int kk = 0; kk < 2; kk++) {
            uint32_t af[2][4];
#pragma unroll
            for (int i = 0; i < 2; i++)
                LDMX4(af[i][0], af[i][1], af[i][2], af[i][3],
                      stg + a_rel + i * 16 * SMPAD + kk * 32);
            uint32_t bf[8][2];
#pragma unroll
            for (int p = 0; p < 4; p++) {
                uint32_t r0, r1, r2, r3;
                LDMX4(r0, r1, r2, r3, stg + b_rel + p * 16 * SMPAD + kk * 32);
                bf[2 * p][0] = r0; bf[2 * p][1] = r1;
                bf[2 * p + 1][0] = r2; bf[2 * p + 1][1] = r3;
            }
#pragma unroll
            for (int i = 0; i < 2; i++)
#pragma unroll
                for (int j = 0; j < 8; j++)
                    MMA16816F16(acc[i][j], af[i][0], af[i][1], af[i][2], af[i][3],
                                bf[j][0], bf[j][1]);
        }
    }
    CP_WAIT(0);

    // ---- fused epilogue: two 128-row halves through smem ----
    float* tile = (float*)sm;
    const int nt = blockIdx.x;             // 0..15 q, 16..19 k, 20..23 v
    const int cr = lane >> 2, cc = (lane & 3) << 1;

#pragma unroll 1
    for (int half = 0; half < 2; half++) {
        __syncthreads();
        if ((wm >> 2) == half) {
            const int lwm = wm & 3;
#pragma unroll
            for (int i = 0; i < 2; i++) {
                const int row = lwm * 32 + i * 16 + cr;
#pragma unroll
                for (int j = 0; j < 8; j++) {
                    const int col = wn * 64 + j * 8 + cc;
                    tile[row * EPAD + col]           = acc[i][j][0];
                    tile[row * EPAD + col + 1]       = acc[i][j][1];
                    tile[(row + 8) * EPAD + col]     = acc[i][j][2];
                    tile[(row + 8) * EPAD + col + 1] = acc[i][j][3];
                }
            }
        }
        __syncthreads();

        const int mbase = m0 + half * 128;
        if (nt < 20) {
            const int r = tid >> 2, q = tid & 3;
            const int mrow = mbase + r;
            const int t = mrow & (T_ - 1);
            float o1v[16], o2v[16];
            float ss = 0.0f;
#pragma unroll
            for (int i = 0; i < 16; i += 4) {
                float4 x1 = *(float4*)&tile[r * EPAD + q * 16 + i];
                float4 x2 = *(float4*)&tile[r * EPAD + 64 + q * 16 + i];
                float4 cv = *(const float4*)(cosp + t * 64 + q * 16 + i);
                float4 sv = *(const float4*)(sinp + t * 64 + q * 16 + i);
                o1v[i]     = x1.x * cv.x + x2.x * sv.x;
                o2v[i]     = x2.x * cv.x - x1.x * sv.x;
                o1v[i + 1] = x1.y * cv.y + x2.y * sv.y;
                o2v[i + 1] = x2.y * cv.y - x1.y * sv.y;
                o1v[i + 2] = x1.z * cv.z + x2.z * sv.z;
                o2v[i + 2] = x2.z * cv.z - x1.z * sv.z;
                o1v[i + 3] = x1.w * cv.w + x2.w * sv.w;
                o2v[i + 3] = x2.w * cv.w - x1.w * sv.w;
#pragma unroll
                for (int e = 0; e < 4; e++)
                    ss += o1v[i + e] * o1v[i + e] + o2v[i + e] * o2v[i + e];
            }
            ss += __shfl_xor_sync(0xffffffffu, ss, 1);
            ss += __shfl_xor_sync(0xffffffffu, ss, 2);
            const float rn = rsqrtf(ss * (1.0f / 128.0f) + 1e-5f);

            __half* dst = (nt < 16)
                ? (q16 + (size_t)mrow * 2048 + (size_t)nt * 128)
                : (k2 + ((size_t)((mrow >> 11) * KVH_ + (nt - 16)) * T_ + t) * 128);
            __half2 w1[8], w2[8];
#pragma unroll
            for (int i = 0; i < 8; i++) {
                w1[i] = __floats2half2_rn(o1v[2 * i] * rn, o1v[2 * i + 1] * rn);
                w2[i] = __floats2half2_rn(o2v[2 * i] * rn, o2v[2 * i + 1] * rn);
            }
            *(uint4*)(dst + q * 16)          = *(uint4*)&w1[0];
            *(uint4*)(dst + q * 16 + 8)      = *(uint4*)&w1[4];
            *(uint4*)(dst + 64 + q * 16)     = *(uint4*)&w2[0];
            *(uint4*)(dst + 64 + q * 16 + 8) = *(uint4*)&w2[4];
        } else {
            const int d = tid >> 2, rc = tid & 3;
            const int kvh = nt - 20;
            const int b = mbase >> 11;
            const int t0 = mbase & (T_ - 1);
            __half hv[32];
#pragma unroll
            for (int rr = 0; rr < 32; rr++)
                hv[rr] = __float2half_rn(tile[(rc * 32 + rr) * EPAD + d]);
            __half* dst = vt + ((size_t)(b * KVH_ + kvh) * 128 + d) * T_ + t0 + rc * 32;
#pragma unroll
            for (int c = 0; c < 4; c++)
                *(uint4*)(dst + c * 8) = *(uint4*)&hv[c * 8];
        }
    }
}

// ================= plain fp16 GEMM (output projection) =================
__global__ __launch_bounds__(512, 1)
void gemm_f16(const __half* __restrict__ A, const __half* __restrict__ Bt,
              float* __restrict__ C, int N) {
    extern __shared__ uint8_t sm[];
    const uint32_t smb = smem_u32(sm);

    const int tid = threadIdx.x;
    const int lane = tid & 31, wid = tid >> 5;
    const int wm = wid >> 1, wn = wid & 1;
    const int m0 = blockIdx.y * 256, n0 = blockIdx.x * 128;

    const int crow = tid >> 2, c16 = tid & 3;
    const __half* agp0 = A + (size_t)(m0 + crow) * KG_ + c16 * 8;
    const __half* agp1 = agp0 + (size_t)128 * KG_;
    const __half* bgp  = Bt + (size_t)(n0 + crow) * KG_ + c16 * 8;
    const uint32_t sa0_rel = (uint32_t)(crow * SMPAD + c16 * 16);
    const uint32_t sa1_rel = sa0_rel + 128 * SMPAD;
    const uint32_t sb_rel  = (uint32_t)(GASTG + crow * SMPAD + c16 * 16);
    const bool do_b = (crow < 128);

    float acc[2][8][4];
#pragma unroll
    for (int i = 0; i < 2; i++)
#pragma unroll
        for (int j = 0; j < 8; j++)
#pragma unroll
            for (int r = 0; r < 4; r++) acc[i][j][r] = 0.0f;

    const int nK = KG_ / 32;

#pragma unroll
    for (int s = 0; s < 3; s++) {
        const uint32_t base = smb + s * GSTAGE_B;
        const int k0 = s * 32;
        CP_ASYNC16(base + sa0_rel, agp0 + k0);
        CP_ASYNC16(base + sa1_rel, agp1 + k0);
        if (do_b) CP_ASYNC16(base + sb_rel, bgp + k0);
        CP_COMMIT();
    }

    const int lj = lane >> 3, lr = lane & 7;
    const uint32_t a_rel = (uint32_t)((wm * 32 + ((lj & 1) << 3) + lr) * SMPAD + ((lj >> 1) << 4));
    const uint32_t b_rel = (uint32_t)(GASTG + (wn * 64 + ((lj >> 1) << 3) + lr) * SMPAD + ((lj & 1) << 4));

    for (int it = 0; it < nK; it++) {
        CP_WAIT(2);
        __syncthreads();
        const int is = it + 3;
        if (is < nK) {
            const uint32_t base = smb + (is & 3) * GSTAGE_B;
            const int k0 = is * 32;
            CP_ASYNC16(base + sa0_rel, agp0 + k0);
            CP_ASYNC16(base + sa1_rel, agp1 + k0);
            if (do_b) CP_ASYNC16(base + sb_rel, bgp + k0);
        }
        CP_COMMIT();

        const uint32_t stg = smb + (it & 3) * GSTAGE_B;
#pragma unroll
        for (int kk = 0; kk < 2; kk++) {
            uint32_t af[2][4];
#pragma unroll
            for (int i = 0; i < 2; i++)
                LDMX4(af[i][0], af[i][1], af[i][2], af[i][3],
                      stg + a_rel + i * 16 * SMPAD + kk * 32);
            uint32_t bf[8][2];
#pragma unroll
            for (int p = 0; p < 4; p++) {
                uint32_t r0, r1, r2, r3;
                LDMX4(r0, r1, r2, r3, stg + b_rel + p * 16 * SMPAD + kk * 32);
                bf[2 * p][0] = r0; bf[2 * p][1] = r1;
                bf[2 * p + 1][0] = r2; bf[2 * p + 1][1] = r3;
            }
#pragma unroll
            for (int i = 0; i < 2; i++)
#pragma unroll
                for (int j = 0; j < 8; j++)
                    MMA16816F16(acc[i][j], af[i][0], af[i][1], af[i][2], af[i][3],
                                bf[j][0], bf[j][1]);
        }
    }

    const int cr = lane >> 2, cc = (lane & 3) << 1;
#pragma unroll
    for (int i = 0; i < 2; i++) {
        const int mrow = m0 + wm * 32 + i * 16 + cr;
#pragma unroll
        for (int j = 0; j < 8; j++) {
            const int col = n0 + wn * 64 + j * 8 + cc;
            *(float2*)(C + (size_t)mrow * N + col)       = make_float2(acc[i][j][0], acc[i][j][1]);
            *(float2*)(C + (size_t)(mrow + 8) * N + col) = make_float2(acc[i][j][2], acc[i][j][3]);
        }
    }
}

// ---------------- tensor-core flash attention (pure fp16, single-barrier softmax) ----------------
#define AKS 272
#define AVS2 144
#define SM_Q   0
#define SM_K0  (64 * AKS)
#define SM_K1  (SM_K0 + 64 * AKS)
#define SM_V0  (SM_K1 + 64 * AKS)
#define SM_V1  (SM_V0 + 128 * AVS2)
#define SM_RED (SM_V1 + 128 * AVS2)
#define ATT_SMEM (SM_RED + 1024)       // 90112
#define ATT_SCALE 0.08838834764831845f

__global__ __launch_bounds__(256, 2)
void attn_mma_kernel(const __half* __restrict__ q16,
                     const __half* __restrict__ k2,
                     const __half* __restrict__ vt,
                     __half* __restrict__ ys) {
    extern __shared__ uint8_t sm[];
    const uint32_t smb = smem_u32(sm);
    float* redmax = (float*)(sm + SM_RED);          // [2][64]
    float* redsum = (float*)(sm + SM_RED + 512);    // [2][64]

    const int tid = threadIdx.x;
    const int lane = tid & 31, wid = tid >> 5;
    const int wm = wid >> 1, wn = wid & 1;
    const int qtile = 31 - blockIdx.x;
    const int bh = blockIdx.y;
    const int b  = bh >> 4;
    const int h  = bh & 15;
    const int kv = h >> 2;
    const int q0 = qtile * 64;

    const __half* k2b = k2 + (size_t)(b * KVH_ + kv) * T_ * 128;
    const __half* vtb = vt + (size_t)(b * KVH_ + kv) * 128 * T_;
    const __half* q16b = q16 + (size_t)(b * T_ + q0) * 2048 + (size_t)h * 128;

    const int krow = tid >> 2, kc = tid & 3;
    const int vrow = tid >> 1, vc = tid & 1;
    const uint32_t kdst_rel = (uint32_t)(krow * AKS);
    const uint32_t vdst_rel = (uint32_t)(vrow * AVS2);

    {
#pragma unroll
        for (int i = 0; i < 4; i++) {
            int c = kc + i * 4;
            CP_ASYNC16(smb + SM_Q + kdst_rel + c * 16, q16b + (size_t)krow * 2048 + c * 8);
        }
        const __half* src = k2b + (size_t)krow * 128;
#pragma unroll
        for (int i = 0; i < 4; i++) {
            int c = kc + i * 4;
            CP_ASYNC16(smb + SM_K0 + kdst_rel + c * 16, src + c * 8);
        }
        const __half* srow = vtb + (size_t)vrow * T_;
#pragma unroll
        for (int i = 0; i < 4; i++) {
            int c = vc + i * 2;
            CP_ASYNC16(smb + SM_V0 + vdst_rel + c * 16, srow + c * 8);
        }
        CP_COMMIT();
    }

    const int lj = lane >> 3, lr = lane & 7;
    const uint32_t a_off = smb + SM_Q + (uint32_t)((wm * 16 + ((lj & 1) << 3) + lr) * AKS + ((lj >> 1) << 4));
    const uint32_t b_rel = (uint32_t)((wn * 32 + ((lj >> 1) << 3) + lr) * AKS + ((lj & 1) << 4));
    const uint32_t v_rel = (uint32_t)((((lj >> 1) << 3) + lr) * AVS2 + ((lj & 1) << 4));

    const int ra = lane >> 2;
    const int row_a = wm * 16 + ra, row_b = row_a + 8;
    const int colb = wn * 32 + 2 * (lane & 3);
    float m_a = -FLT_MAX, m_b = -FLT_MAX, l_a = 0.0f, l_b = 0.0f;

    float o[16][4];
#pragma unroll
    for (int j = 0; j < 16; j++)
#pragma unroll
        for (int r = 0; r < 4; r++) o[j][r] = 0.0f;

    for (int jt = 0; jt <= qtile; jt++) {
        const int buf = jt & 1;
        const uint32_t sK = smb + (buf ? SM_K1 : SM_K0);
        const uint32_t sV = smb + (buf ? SM_V1 : SM_V0);

        CP_WAIT(0);
        __syncthreads();

        if (jt < qtile) {
            const int j1 = (jt + 1) * 64;
            const uint32_t dK = smb + (buf ? SM_K0 : SM_K1);
            const uint32_t dV = smb + (buf ? SM_V0 : SM_V1);
            const __half* src = k2b + (size_t)(j1 + krow) * 128;
#pragma unroll
            for (int i = 0; i < 4; i++) {
                int c = kc + i * 4;
                CP_ASYNC16(dK + kdst_rel + c * 16, src + c * 8);
            }
            const __half* srow = vtb + (size_t)vrow * T_ + j1;
#pragma unroll
            for (int i = 0; i < 4; i++) {
                int c = vc + i * 2;
                CP_ASYNC16(dV + vdst_rel + c * 16, srow + c * 8);
            }
        }
        CP_COMMIT();

        // ---- S = Qh Kh^T ----
        float s_[4][4];
#pragma unroll
        for (int j = 0; j < 4; j++)
#pragma unroll
            for (int r = 0; r < 4; r++) s_[j][r] = 0.0f;

#pragma unroll
        for (int kk = 0; kk < 8; kk++) {
            uint32_t af[4];
            LDMX4(af[0], af[1], af[2], af[3], a_off + 32 * kk);
            uint32_t bf[4][2];
#pragma unroll
            for (int p = 0; p < 2; p++) {
                uint32_t r0, r1, r2, r3;
                LDMX4(r0, r1, r2, r3, sK + b_rel + p * 16 * AKS + 32 * kk);
                bf[2 * p][0] = r0; bf[2 * p][1] = r1;
                bf[2 * p + 1][0] = r2; bf[2 * p + 1][1] = r3;
            }
#pragma unroll
            for (int j = 0; j < 4; j++)
                MMA16816F16(s_[j], af[0], af[1], af[2], af[3], bf[j][0], bf[j][1]);
        }

        // ---- single-barrier online softmax ----
        const bool diag = (jt == qtile);
        float mxa = -FLT_MAX, mxb = -FLT_MAX;
#pragma unroll
        for (int j = 0; j < 4; j++)
#pragma unroll
            for (int e = 0; e < 2; e++) {
                int cg = colb + 8 * j + e;
                float va = s_[j][e] * ATT_SCALE;
                if (diag && cg > row_a) va = -FLT_MAX;
                s_[j][e] = va; mxa = fmaxf(mxa, va);
                float vb = s_[j][e + 2] * ATT_SCALE;
                if (diag && cg > row_b) vb = -FLT_MAX;
                s_[j][e + 2] = vb; mxb = fmaxf(mxb, vb);
            }
        mxa = fmaxf(mxa, __shfl_xor_sync(0xffffffffu, mxa, 1));
        mxa = fmaxf(mxa, __shfl_xor_sync(0xffffffffu, mxa, 2));
        mxb = fmaxf(mxb, __shfl_xor_sync(0xffffffffu, mxb, 1));
        mxb = fmaxf(mxb, __shfl_xor_sync(0xffffffffu, mxb, 2));

        // local p = exp(s - m_loc), local sums (NaN-guarded subtraction base)
        const float mga = fmaxf(mxa, -1e30f), mgb = fmaxf(mxb, -1e30f);
        float sa = 0.0f, sb = 0.0f;
#pragma unroll
        for (int j = 0; j < 4; j++)
#pragma unroll
            for (int e = 0; e < 2; e++) {
                float pa = __expf(s_[j][e] - mga);
                s_[j][e] = pa; sa += pa;
                float pb = __expf(s_[j][e + 2] - mgb);
                s_[j][e + 2] = pb; sb += pb;
            }
        sa += __shfl_xor_sync(0xffffffffu, sa, 1);
        sa += __shfl_xor_sync(0xffffffffu, sa, 2);
        sb += __shfl_xor_sync(0xffffffffu, sb, 1);
        sb += __shfl_xor_sync(0xffffffffu, sb, 2);
        if ((lane & 3) == 0) {
            redmax[wn * 64 + row_a] = mxa;
            redmax[wn * 64 + row_b] = mxb;
            redsum[wn * 64 + row_a] = sa;
            redsum[wn * 64 + row_b] = sb;
        }
        __syncthreads();

        // merge halves
        float m0a = redmax[row_a],      m1a = redmax[64 + row_a];
        float m0b = redmax[row_b],      m1b = redmax[64 + row_b];
        float s0a = redsum[row_a],      s1a = redsum[64 + row_a];
        float s0b = redsum[row_b],      s1b = redsum[64 + row_b];
        float mna = fmaxf(m_a, fmaxf(m0a, m1a));
        float mnb = fmaxf(m_b, fmaxf(m0b, m1b));
        float fa = __expf(m_a - mna), fb = __expf(m_b - mnb);
        float e0a = __expf(m0a - mna), e1a = __expf(m1a - mna);
        float e0b = __expf(m0b - mnb), e1b = __expf(m1b - mnb);
        l_a = l_a * fa + s0a * e0a + s1a * e1a;
        l_b = l_b * fb + s0b * e0b + s1b * e1b;
        m_a = mna; m_b = mnb;
        const float fowna = wn ? e1a : e0a;   // own-half P rescale
        const float fownb = wn ? e1b : e0b;

#pragma unroll
        for (int j = 0; j < 16; j++) {
            o[j][0] *= fa; o[j][1] *= fa;
            o[j][2] *= fb; o[j][3] *= fb;
        }

        // ---- P fragments (fp16, rescaled by own-half factor) ----
        uint32_t php0[4], php1[4];
#pragma unroll
        for (int j = 0; j < 4; j++) {
            __half2 h01 = __floats2half2_rn(s_[j][0] * fowna, s_[j][1] * fowna);
            __half2 h23 = __floats2half2_rn(s_[j][2] * fownb, s_[j][3] * fownb);
            php0[j] = *(uint32_t*)&h01;
            php1[j] = *(uint32_t*)&h23;
        }

        // ---- O += Ph Vh ----
        {
            const uint32_t bbase = wn * 64u;
#pragma unroll
            for (int kk2 = 0; kk2 < 2; kk2++) {
                uint32_t a0 = php0[2 * kk2];
                uint32_t a1 = php1[2 * kk2];
                uint32_t a2 = php0[2 * kk2 + 1];
                uint32_t a3 = php1[2 * kk2 + 1];
                uint32_t vb[16][2];
#pragma unroll
                for (int p = 0; p < 8; p++) {
                    uint32_t r0, r1, r2, r3;
                    LDMX4(r0, r1, r2, r3, sV + v_rel + p * 16 * AVS2 + bbase + 32 * kk2);
                    vb[2 * p][0] = r0; vb[2 * p][1] = r1;
                    vb[2 * p + 1][0] = r2; vb[2 * p + 1][1] = r3;
                }
#pragma unroll
                for (int j = 0; j < 16; j++)
                    MMA16816F16(o[j], a0, a1, a2, a3, vb[j][0], vb[j][1]);
            }
        }
    }

    __syncthreads();
    float* Ob = (float*)sm;
    if (wn == 1) {
#pragma unroll
        for (int j = 0; j < 16; j++) {
            int col = 8 * j + 2 * (lane & 3);
            *(float2*)&Ob[row_a * 132 + col] = make_float2(o[j][0], o[j][1]);
            *(float2*)&Ob[row_b * 132 + col] = make_float2(o[j][2], o[j][3]);
        }
    }
    __syncthreads();
    if (wn == 0) {
        float inva = 1.0f / l_a, invb = 1.0f / l_b;
        __half* base = ys + (size_t)(b * T_ + q0) * KG_ + h * 128;
#pragma unroll
        for (int j = 0; j < 16; j++) {
            int col = 8 * j + 2 * (lane & 3);
            float2 pa = *(float2*)&Ob[row_a * 132 + col];
            float2 pb = *(float2*)&Ob[row_b * 132 + col];
            *(__half2*)(base + (size_t)row_a * KG_ + col) =
                __floats2half2_rn((o[j][0] + pa.x) * inva, (o[j][1] + pa.y) * inva);
            *(__half2*)(base + (size_t)row_b * KG_ + col) =
                __floats2half2_rn((o[j][2] + pb.x) * invb, (o[j][3] + pb.y) * invb);
        }
    }
}

// ---------------- launch ----------------
extern "C" void kernel_launch(void* const* d_in, const int* in_sizes, int n_in,
                              void* d_out, int out_size) {
    const float* x    = (const float*)d_in[0];
    const float* cosp = (const float*)d_in[1];
    const float* sinp = (const float*)d_in[2];
    const float* wq   = (const float*)d_in[3];
    const float* wk   = (const float*)d_in[4];
    const float* wv   = (const float*)d_in[5];
    const float* wo   = (const float*)d_in[6];
    float* out = (float*)d_out;

    __half *xs, *wb1, *wb2, *ys, *q16, *k2, *vt;
    cudaGetSymbolAddress((void**)&xs,  g_xs);
    cudaGetSymbolAddress((void**)&wb1, g_wb1);
    cudaGetSymbolAddress((void**)&wb2, g_wb2);
    cudaGetSymbolAddress((void**)&ys,  g_ys);
    cudaGetSymbolAddress((void**)&q16, g_q16);
    cudaGetSymbolAddress((void**)&k2,  g_k2);
    cudaGetSymbolAddress((void**)&vt,  g_vt);

    cudaFuncSetAttribute(attn_mma_kernel, cudaFuncAttributeMaxDynamicSharedMemorySize, ATT_SMEM);
    cudaFuncSetAttribute(gemm_f16, cudaFuncAttributeMaxDynamicSharedMemorySize, GSMEM);
    cudaFuncSetAttribute(gemm_qkv, cudaFuncAttributeMaxDynamicSharedMemorySize, GSMEM);

    dim3 tb(32, 8);
    conv_a_kernel<<<(M_ * 2048 / 4) / 256, 256>>>(x, xs);
    tsplit_b_kernel<<<dim3(2048 / 32, 2048 / 32), tb>>>(wq, wb1, 2048);
    tsplit_b_kernel<<<dim3(512  / 32, 2048 / 32), tb>>>(wk, wb1 + (size_t)2048 * KG_, 512);
    tsplit_b_kernel<<<dim3(512  / 32, 2048 / 32), tb>>>(wv, wb1 + (size_t)2560 * KG_, 512);
    tsplit_b_kernel<<<dim3(2048 / 32, 2048 / 32), tb>>>(wo, wb2, 2048);

    gemm_qkv<<<dim3(3072 / 128, M_ / 256), 512, GSMEM>>>(xs, wb1, cosp, sinp, q16, k2, vt);
    attn_mma_kernel<<<dim3(32, 32), 256, ATT_SMEM>>>(q16, k2, vt, ys);
    gemm_f16<<<dim3(2048 / 128, M_ / 256), 512, GSMEM>>>(ys, wb2, out, 2048);
}